// round 5
// baseline (speedup 1.0000x reference)
#include <cuda_runtime.h>
#include <cuda_bf16.h>

// Wilson Dslash, 32^4 lattice, half-spinor formulation.
// - mu unrolled (static projector structure), hop runtime (register relief)
// - U staged through shared memory, coalesced; dagger (transpose+conj) applied
//   at staging-store time so the compute path is hop-uniform (no selects)
// - psi neighbor loads issued BEFORE the staging barrier so their DRAM/L2
//   latency hides under the staging + __syncthreads.

#define LAT 32
#define VOL (LAT * LAT * LAT * LAT)
#define NT 256
#define UELEM (NT * 9)

__global__ __launch_bounds__(NT, 2)
void dslash_kernel(const float* __restrict__ psi_re, const float* __restrict__ psi_im,
                   const float* __restrict__ U_re,   const float* __restrict__ U_im,
                   float* __restrict__ out)
{
    __shared__ float sUr[2][UELEM];
    __shared__ float sUi[2][UELEM];

    const int tid  = threadIdx.x;
    const int base = blockIdx.x * NT;
    const int site = base + tid;

    float accr[12], acci[12];
#pragma unroll
    for (int k = 0; k < 12; k++) { accr[k] = 0.f; acci[k] = 0.f; }

#pragma unroll
    for (int mu = 0; mu < 4; mu++) {
        const int shift = (mu == 0) ? 15 : (mu == 1) ? 10 : (mu == 2) ? 5 : 0;
        const int sm = 1 << shift;

#pragma unroll 1
        for (int hop = 0; hop < 2; hop++) {   // 0 = fwd (P-, U), 1 = bwd (P+, U^dag)
            const float s = hop ? 1.f : -1.f;

            // ---- neighbor site & EARLY psi issue (latency hides under staging) ----
            const int cm = (site >> shift) & 31;
            const int nb = hop ? (site + ((cm == 0)  ? 31 * sm : -sm))
                               : (site + ((cm == 31) ? -31 * sm : sm));

            float pr[12], pi[12];
            {
                const float4* q4r = reinterpret_cast<const float4*>(psi_re + (size_t)nb * 12);
                const float4* q4i = reinterpret_cast<const float4*>(psi_im + (size_t)nb * 12);
#pragma unroll
                for (int k = 0; k < 3; k++) {
                    float4 a = q4r[k];
                    pr[4*k+0] = a.x; pr[4*k+1] = a.y; pr[4*k+2] = a.z; pr[4*k+3] = a.w;
                    float4 b = q4i[k];
                    pi[4*k+0] = b.x; pi[4*k+1] = b.y; pi[4*k+2] = b.z; pi[4*k+3] = b.w;
                }
            }

            // ---- cooperative coalesced staging of U slice; apply dagger here ----
#pragma unroll
            for (int it = 0; it < UELEM / NT; it++) {
                const int idx = it * NT + tid;
                const int l = idx / 9;
                const int k = idx - l * 9;
                int s2 = base + l;
                if (hop) {
                    const int c2 = (s2 >> shift) & 31;
                    s2 += (c2 == 0) ? 31 * sm : -sm;
                }
                const size_t g = ((size_t)s2 * 4 + mu) * 9 + k;
                const float vr = U_re[g];
                const float vi = U_im[g];
                const int r = k / 3, c = k - 3 * r;
                const int dk = hop ? (c * 3 + r) : k;      // transpose for dagger
                sUr[hop][l * 9 + dk] = vr;
                sUi[hop][l * 9 + dk] = hop ? -vi : vi;     // conjugate for dagger
            }
            __syncthreads();

            // ---- project to half-spinor (mu static, s runtime) ----
            float hr0[3], hi0[3], hr1[3], hi1[3];
#pragma unroll
            for (int c = 0; c < 3; c++) {
                if (mu == 0) {          // h0 = p0 + s*i*p3 ; h1 = p1 + s*i*p2
                    hr0[c] = pr[c]   - s * pi[9+c];  hi0[c] = pi[c]   + s * pr[9+c];
                    hr1[c] = pr[3+c] - s * pi[6+c];  hi1[c] = pi[3+c] + s * pr[6+c];
                } else if (mu == 1) {   // h0 = p0 - s*p3 ; h1 = p1 + s*p2
                    hr0[c] = pr[c]   - s * pr[9+c];  hi0[c] = pi[c]   - s * pi[9+c];
                    hr1[c] = pr[3+c] + s * pr[6+c];  hi1[c] = pi[3+c] + s * pi[6+c];
                } else if (mu == 2) {   // h0 = p0 + s*i*p2 ; h1 = p1 - s*i*p3
                    hr0[c] = pr[c]   - s * pi[6+c];  hi0[c] = pi[c]   + s * pr[6+c];
                    hr1[c] = pr[3+c] + s * pi[9+c];  hi1[c] = pi[3+c] - s * pr[9+c];
                } else {                // h0 = p0 + s*p2 ; h1 = p1 + s*p3
                    hr0[c] = pr[c]   + s * pr[6+c];  hi0[c] = pi[c]   + s * pi[6+c];
                    hr1[c] = pr[3+c] + s * pr[9+c];  hi1[c] = pi[3+c] + s * pi[9+c];
                }
            }

            // ---- U from smem (already transposed/conjugated for bwd) ----
            float ur[9], ui[9];
            {
                const float* br = &sUr[hop][tid * 9];
                const float* bi = &sUi[hop][tid * 9];
#pragma unroll
                for (int k = 0; k < 9; k++) { ur[k] = br[k]; ui[k] = bi[k]; }
            }

            // ---- 2 complex color matvecs + reconstruction accumulate ----
#pragma unroll
            for (int i = 0; i < 3; i++) {
                float xr0 = 0.f, xi0 = 0.f, xr1 = 0.f, xi1 = 0.f;
#pragma unroll
                for (int j = 0; j < 3; j++) {
                    const float a = ur[i*3+j], b = ui[i*3+j];
                    xr0 += a * hr0[j] - b * hi0[j];
                    xi0 += a * hi0[j] + b * hr0[j];
                    xr1 += a * hr1[j] - b * hi1[j];
                    xi1 += a * hi1[j] + b * hr1[j];
                }
                accr[i]   += xr0;  acci[i]   += xi0;
                accr[3+i] += xr1;  acci[3+i] += xi1;
                if (mu == 0) {          // acc2 += -s*i*x1 ; acc3 += -s*i*x0
                    accr[6+i] += s * xi1;  acci[6+i] -= s * xr1;
                    accr[9+i] += s * xi0;  acci[9+i] -= s * xr0;
                } else if (mu == 1) {   // acc2 += s*x1 ; acc3 += -s*x0
                    accr[6+i] += s * xr1;  acci[6+i] += s * xi1;
                    accr[9+i] -= s * xr0;  acci[9+i] -= s * xi0;
                } else if (mu == 2) {   // acc2 += -s*i*x0 ; acc3 += s*i*x1
                    accr[6+i] += s * xi0;  acci[6+i] -= s * xr0;
                    accr[9+i] -= s * xi1;  acci[9+i] += s * xr1;
                } else {                // acc2 += s*x0 ; acc3 += s*x1
                    accr[6+i] += s * xr0;  acci[6+i] += s * xi0;
                    accr[9+i] += s * xr1;  acci[9+i] += s * xi1;
                }
            }
        }
    }

    // ---- scale by -0.5 and store ----
    float* orp = out + (size_t)site * 12;
    float* oip = out + (size_t)VOL * 12 + (size_t)site * 12;
#pragma unroll
    for (int k = 0; k < 3; k++) {
        float4 a, b;
        a.x = -0.5f * accr[4*k+0]; a.y = -0.5f * accr[4*k+1];
        a.z = -0.5f * accr[4*k+2]; a.w = -0.5f * accr[4*k+3];
        b.x = -0.5f * acci[4*k+0]; b.y = -0.5f * acci[4*k+1];
        b.z = -0.5f * acci[4*k+2]; b.w = -0.5f * acci[4*k+3];
        reinterpret_cast<float4*>(orp)[k] = a;
        reinterpret_cast<float4*>(oip)[k] = b;
    }
}

extern "C" void kernel_launch(void* const* d_in, const int* in_sizes, int n_in,
                              void* d_out, int out_size) {
    const float* psi_re = (const float*)d_in[0];
    const float* psi_im = (const float*)d_in[1];
    const float* U_re   = (const float*)d_in[2];
    const float* U_im   = (const float*)d_in[3];
    // d_in[4..7]: projector matrices — fixed DeGrand-Rossi I -/+ gamma_mu,
    // rank-2 structure exploited analytically.
    float* out = (float*)d_out;

    dslash_kernel<<<VOL / NT, NT>>>(psi_re, psi_im, U_re, U_im, out);
}

// round 7
// speedup vs baseline: 1.1452x; 1.1452x over previous
#include <cuda_runtime.h>
#include <cuda_bf16.h>

// Wilson Dslash, 32^4 lattice, half-spinor formulation.
// - mu unrolled (static projector structure), hop runtime (register relief)
// - U staged WARP-LOCALLY through shared memory (coalesced loads, private
//   per-warp strip, __syncwarp only -- no block barriers at all)
// - dagger applied at read time (transpose+conj via per-element select)
// - psi neighbor loads issued before staging for MLP.

#define LAT 32
#define VOL (LAT * LAT * LAT * LAT)
#define NT 256
#define NWARP (NT / 32)
#define WELEM (32 * 9)   // 288 floats per warp per array

__global__ __launch_bounds__(NT, 2)
void dslash_kernel(const float* __restrict__ psi_re, const float* __restrict__ psi_im,
                   const float* __restrict__ U_re,   const float* __restrict__ U_im,
                   float* __restrict__ out)
{
    __shared__ float sUr[NWARP][WELEM];
    __shared__ float sUi[NWARP][WELEM];

    const int tid    = threadIdx.x;
    const int lane   = tid & 31;
    const int w      = tid >> 5;
    const int base_w = blockIdx.x * NT + w * 32;
    const int site   = base_w + lane;

    float accr[12], acci[12];
#pragma unroll
    for (int k = 0; k < 12; k++) { accr[k] = 0.f; acci[k] = 0.f; }

#pragma unroll
    for (int mu = 0; mu < 4; mu++) {
        const int shift = (mu == 0) ? 15 : (mu == 1) ? 10 : (mu == 2) ? 5 : 0;
        const int sm = 1 << shift;

#pragma unroll 1
        for (int hop = 0; hop < 2; hop++) {   // 0 = fwd (P-, U), 1 = bwd (P+, U^dag)
            const float s = hop ? 1.f : -1.f;

            // ---- neighbor site & early psi issue (MLP) ----
            const int cm = (site >> shift) & 31;
            const int nb = hop ? (site + ((cm == 0)  ? 31 * sm : -sm))
                               : (site + ((cm == 31) ? -31 * sm : sm));

            float pr[12], pi[12];
            {
                const float4* q4r = reinterpret_cast<const float4*>(psi_re + (size_t)nb * 12);
                const float4* q4i = reinterpret_cast<const float4*>(psi_im + (size_t)nb * 12);
#pragma unroll
                for (int k = 0; k < 3; k++) {
                    float4 a = q4r[k];
                    pr[4*k+0] = a.x; pr[4*k+1] = a.y; pr[4*k+2] = a.z; pr[4*k+3] = a.w;
                    float4 b = q4i[k];
                    pi[4*k+0] = b.x; pi[4*k+1] = b.y; pi[4*k+2] = b.z; pi[4*k+3] = b.w;
                }
            }

            // ---- warp-local coalesced staging of this warp's U slice ----
#pragma unroll
            for (int it = 0; it < 9; it++) {
                const int idx = it * 32 + lane;          // 0..287
                const int l = idx / 9;                   // local site 0..31
                const int k = idx - l * 9;               // element 0..8
                int s2 = base_w + l;
                if (hop) {
                    const int c2 = (s2 >> shift) & 31;
                    s2 += (c2 == 0) ? 31 * sm : -sm;
                }
                const size_t g = ((size_t)s2 * 4 + mu) * 9 + k;
                sUr[w][idx] = U_re[g];
                sUi[w][idx] = U_im[g];
            }
            __syncwarp();

            // ---- project to half-spinor (mu static, s runtime) ----
            float hr0[3], hi0[3], hr1[3], hi1[3];
#pragma unroll
            for (int c = 0; c < 3; c++) {
                if (mu == 0) {          // h0 = p0 + s*i*p3 ; h1 = p1 + s*i*p2
                    hr0[c] = pr[c]   - s * pi[9+c];  hi0[c] = pi[c]   + s * pr[9+c];
                    hr1[c] = pr[3+c] - s * pi[6+c];  hi1[c] = pi[3+c] + s * pr[6+c];
                } else if (mu == 1) {   // h0 = p0 - s*p3 ; h1 = p1 + s*p2
                    hr0[c] = pr[c]   - s * pr[9+c];  hi0[c] = pi[c]   - s * pi[9+c];
                    hr1[c] = pr[3+c] + s * pr[6+c];  hi1[c] = pi[3+c] + s * pi[6+c];
                } else if (mu == 2) {   // h0 = p0 + s*i*p2 ; h1 = p1 - s*i*p3
                    hr0[c] = pr[c]   - s * pi[6+c];  hi0[c] = pi[c]   + s * pr[6+c];
                    hr1[c] = pr[3+c] + s * pi[9+c];  hi1[c] = pi[3+c] - s * pr[9+c];
                } else {                // h0 = p0 + s*p2 ; h1 = p1 + s*p3
                    hr0[c] = pr[c]   + s * pr[6+c];  hi0[c] = pi[c]   + s * pi[6+c];
                    hr1[c] = pr[3+c] + s * pr[9+c];  hi1[c] = pi[3+c] + s * pi[9+c];
                }
            }

            // ---- U (or U^dag) from warp smem; transpose/conj selected at read ----
            float ur[9], ui[9];
            {
                const float* br = &sUr[w][lane * 9];
                const float* bi = &sUi[w][lane * 9];
#pragma unroll
                for (int i = 0; i < 3; i++)
#pragma unroll
                    for (int j = 0; j < 3; j++) {
                        const int src = hop ? (3*j + i) : (3*i + j);
                        ur[3*i+j] = br[src];
                        ui[3*i+j] = -s * bi[src];   // fwd: +b (s=-1), bwd: -b (s=+1)
                    }
            }

            // ---- 2 complex color matvecs + reconstruction accumulate ----
#pragma unroll
            for (int i = 0; i < 3; i++) {
                float xr0 = 0.f, xi0 = 0.f, xr1 = 0.f, xi1 = 0.f;
#pragma unroll
                for (int j = 0; j < 3; j++) {
                    const float a = ur[i*3+j], b = ui[i*3+j];
                    xr0 += a * hr0[j] - b * hi0[j];
                    xi0 += a * hi0[j] + b * hr0[j];
                    xr1 += a * hr1[j] - b * hi1[j];
                    xi1 += a * hi1[j] + b * hr1[j];
                }
                accr[i]   += xr0;  acci[i]   += xi0;
                accr[3+i] += xr1;  acci[3+i] += xi1;
                if (mu == 0) {          // acc2 += -s*i*x1 ; acc3 += -s*i*x0
                    accr[6+i] += s * xi1;  acci[6+i] -= s * xr1;
                    accr[9+i] += s * xi0;  acci[9+i] -= s * xr0;
                } else if (mu == 1) {   // acc2 += s*x1 ; acc3 += -s*x0
                    accr[6+i] += s * xr1;  acci[6+i] += s * xi1;
                    accr[9+i] -= s * xr0;  acci[9+i] -= s * xi0;
                } else if (mu == 2) {   // acc2 += -s*i*x0 ; acc3 += s*i*x1
                    accr[6+i] += s * xi0;  acci[6+i] -= s * xr0;
                    accr[9+i] -= s * xi1;  acci[9+i] += s * xr1;
                } else {                // acc2 += s*x0 ; acc3 += s*x1
                    accr[6+i] += s * xr0;  acci[6+i] += s * xi0;
                    accr[9+i] += s * xr1;  acci[9+i] += s * xi1;
                }
            }
            __syncwarp();   // staged buffer reuse next stage
        }
    }

    // ---- scale by -0.5 and store ----
    float* orp = out + (size_t)site * 12;
    float* oip = out + (size_t)VOL * 12 + (size_t)site * 12;
#pragma unroll
    for (int k = 0; k < 3; k++) {
        float4 a, b;
        a.x = -0.5f * accr[4*k+0]; a.y = -0.5f * accr[4*k+1];
        a.z = -0.5f * accr[4*k+2]; a.w = -0.5f * accr[4*k+3];
        b.x = -0.5f * acci[4*k+0]; b.y = -0.5f * acci[4*k+1];
        b.z = -0.5f * acci[4*k+2]; b.w = -0.5f * acci[4*k+3];
        reinterpret_cast<float4*>(orp)[k] = a;
        reinterpret_cast<float4*>(oip)[k] = b;
    }
}

extern "C" void kernel_launch(void* const* d_in, const int* in_sizes, int n_in,
                              void* d_out, int out_size) {
    const float* psi_re = (const float*)d_in[0];
    const float* psi_im = (const float*)d_in[1];
    const float* U_re   = (const float*)d_in[2];
    const float* U_im   = (const float*)d_in[3];
    // d_in[4..7]: projector matrices — fixed DeGrand-Rossi I -/+ gamma_mu,
    // rank-2 structure exploited analytically.
    float* out = (float*)d_out;

    dslash_kernel<<<VOL / NT, NT>>>(psi_re, psi_im, U_re, U_im, out);
}

// round 8
// speedup vs baseline: 1.1830x; 1.0330x over previous
#include <cuda_runtime.h>
#include <cuda_bf16.h>

// Wilson Dslash, 32^4 lattice, half-spinor formulation.
// Key structure: t (fastest axis, extent 32) == warp width. A warp covers one
// full t-line; every x/y/z-hop neighbor set is another contiguous t-line with a
// warp-uniform offset. So psi AND U are staged warp-locally via fully-coalesced
// LDG.128 into per-warp smem, read back conflict-free (float4 stride 3 is
// coprime with the 8 bank groups; scalar stride 9 coprime with 32).
// t-hops (mu=3) reuse the warp's own line: psi loaded once, read at lane+-1;
// U line staged once for both hops. Outputs transposed through smem and stored
// coalesced. No block barriers anywhere (__syncwarp only).

#define LAT 32
#define VOL (LAT * LAT * LAT * LAT)
#define NT 256
#define NWARP (NT / 32)

__global__ __launch_bounds__(NT, 2)
void dslash_kernel(const float* __restrict__ psi_re, const float* __restrict__ psi_im,
                   const float* __restrict__ U_re,   const float* __restrict__ U_im,
                   float* __restrict__ out)
{
    __shared__ float4 sPr4[NWARP][96];   // one t-line of psi re (32 sites x 3 float4)
    __shared__ float4 sPi4[NWARP][96];
    __shared__ float  sUr[NWARP][288];   // one t-line of U (32 sites x 9)
    __shared__ float  sUi[NWARP][288];

    const int tid    = threadIdx.x;
    const int lane   = tid & 31;
    const int w      = tid >> 5;
    const int base_w = blockIdx.x * NT + w * 32;   // 32-aligned t-line base
    const int site   = base_w + lane;

    const float4* psi_re4 = reinterpret_cast<const float4*>(psi_re);
    const float4* psi_im4 = reinterpret_cast<const float4*>(psi_im);

    float accr[12], acci[12];
#pragma unroll
    for (int k = 0; k < 12; k++) { accr[k] = 0.f; acci[k] = 0.f; }

#pragma unroll
    for (int mu = 0; mu < 4; mu++) {
        const int shift = (mu == 0) ? 15 : (mu == 1) ? 10 : (mu == 2) ? 5 : 0;
        const int sm = 1 << shift;
        const int cmw = (base_w >> shift) & 31;                 // warp-uniform coord
        const int fdelta = (cmw == 31) ? -31 * sm : sm;         // +mu line offset
        const int bdelta = (cmw == 0)  ?  31 * sm : -sm;        // -mu line offset

#pragma unroll 1
        for (int hop = 0; hop < 2; hop++) {   // 0 = fwd (P-, U), 1 = bwd (P+, U^dag)
            const float s = hop ? 1.f : -1.f;

            // ---- stage psi t-line (coalesced). mu==3: own line, once. ----
            float4 par[3], pai[3];
            const bool load_psi = (mu < 3) || (hop == 0);
            int pline = base_w;
            if (mu < 3) pline = base_w + (hop ? bdelta : fdelta);
            if (load_psi) {
#pragma unroll
                for (int r = 0; r < 3; r++) {
                    const int j = r * 32 + lane;
                    par[r] = psi_re4[(size_t)pline * 3 + j];
                    pai[r] = psi_im4[(size_t)pline * 3 + j];
                }
            }

            // ---- stage U t-line (coalesced). fwd: own line; bwd: -mu line;
            //      mu==3: own line serves both hops (stage once). ----
            const bool load_u = (mu < 3) || (hop == 0);
            if (load_u) {
                const int ubase = (mu < 3 && hop) ? (base_w + bdelta) : base_w;
#pragma unroll
                for (int it = 0; it < 9; it++) {
                    const int idx = it * 32 + lane;
                    const int l = idx / 9;
                    const int k = idx - l * 9;
                    const size_t g = ((size_t)(ubase + l) * 4 + mu) * 9 + k;
                    sUr[w][idx] = U_re[g];
                    sUi[w][idx] = U_im[g];
                }
            }
            if (load_psi) {
#pragma unroll
                for (int r = 0; r < 3; r++) {
                    sPr4[w][r * 32 + lane] = par[r];
                    sPi4[w][r * 32 + lane] = pai[r];
                }
            }
            __syncwarp();

            // ---- read my neighbor spinor from smem (conflict-free LDS.128) ----
            const int psl = (mu == 3) ? ((lane + (hop ? 31 : 1)) & 31) : lane;
            float pr[12], pi[12];
#pragma unroll
            for (int r = 0; r < 3; r++) {
                float4 a = sPr4[w][psl * 3 + r];
                pr[4*r+0] = a.x; pr[4*r+1] = a.y; pr[4*r+2] = a.z; pr[4*r+3] = a.w;
                float4 b = sPi4[w][psl * 3 + r];
                pi[4*r+0] = b.x; pi[4*r+1] = b.y; pi[4*r+2] = b.z; pi[4*r+3] = b.w;
            }

            // ---- project to half-spinor (mu static, s runtime) ----
            float hr0[3], hi0[3], hr1[3], hi1[3];
#pragma unroll
            for (int c = 0; c < 3; c++) {
                if (mu == 0) {          // h0 = p0 + s*i*p3 ; h1 = p1 + s*i*p2
                    hr0[c] = pr[c]   - s * pi[9+c];  hi0[c] = pi[c]   + s * pr[9+c];
                    hr1[c] = pr[3+c] - s * pi[6+c];  hi1[c] = pi[3+c] + s * pr[6+c];
                } else if (mu == 1) {   // h0 = p0 - s*p3 ; h1 = p1 + s*p2
                    hr0[c] = pr[c]   - s * pr[9+c];  hi0[c] = pi[c]   - s * pi[9+c];
                    hr1[c] = pr[3+c] + s * pr[6+c];  hi1[c] = pi[3+c] + s * pi[6+c];
                } else if (mu == 2) {   // h0 = p0 + s*i*p2 ; h1 = p1 - s*i*p3
                    hr0[c] = pr[c]   - s * pi[6+c];  hi0[c] = pi[c]   + s * pr[6+c];
                    hr1[c] = pr[3+c] + s * pi[9+c];  hi1[c] = pi[3+c] - s * pr[9+c];
                } else {                // h0 = p0 + s*p2 ; h1 = p1 + s*p3
                    hr0[c] = pr[c]   + s * pr[6+c];  hi0[c] = pi[c]   + s * pi[6+c];
                    hr1[c] = pr[3+c] + s * pr[9+c];  hi1[c] = pi[3+c] + s * pi[9+c];
                }
            }

            // ---- U (or U^dag) from warp smem; mu==3 bwd reads rotated site ----
            const int usl = (mu == 3 && hop) ? ((lane + 31) & 31) : lane;
            float ur[9], ui[9];
            {
                const float* br = &sUr[w][usl * 9];
                const float* bi = &sUi[w][usl * 9];
#pragma unroll
                for (int i = 0; i < 3; i++)
#pragma unroll
                    for (int j = 0; j < 3; j++) {
                        const int src = hop ? (3*j + i) : (3*i + j);
                        ur[3*i+j] = br[src];
                        ui[3*i+j] = -s * bi[src];   // fwd: +b (s=-1), bwd: -b (s=+1)
                    }
            }

            // ---- 2 complex color matvecs + reconstruction accumulate ----
#pragma unroll
            for (int i = 0; i < 3; i++) {
                float xr0 = 0.f, xi0 = 0.f, xr1 = 0.f, xi1 = 0.f;
#pragma unroll
                for (int j = 0; j < 3; j++) {
                    const float a = ur[i*3+j], b = ui[i*3+j];
                    xr0 += a * hr0[j] - b * hi0[j];
                    xi0 += a * hi0[j] + b * hr0[j];
                    xr1 += a * hr1[j] - b * hi1[j];
                    xi1 += a * hi1[j] + b * hr1[j];
                }
                accr[i]   += xr0;  acci[i]   += xi0;
                accr[3+i] += xr1;  acci[3+i] += xi1;
                if (mu == 0) {          // acc2 += -s*i*x1 ; acc3 += -s*i*x0
                    accr[6+i] += s * xi1;  acci[6+i] -= s * xr1;
                    accr[9+i] += s * xi0;  acci[9+i] -= s * xr0;
                } else if (mu == 1) {   // acc2 += s*x1 ; acc3 += -s*x0
                    accr[6+i] += s * xr1;  acci[6+i] += s * xi1;
                    accr[9+i] -= s * xr0;  acci[9+i] -= s * xi0;
                } else if (mu == 2) {   // acc2 += -s*i*x0 ; acc3 += s*i*x1
                    accr[6+i] += s * xi0;  acci[6+i] -= s * xr0;
                    accr[9+i] -= s * xi1;  acci[9+i] += s * xr1;
                } else {                // acc2 += s*x0 ; acc3 += s*x1
                    accr[6+i] += s * xr0;  acci[6+i] += s * xi0;
                    accr[9+i] += s * xr1;  acci[9+i] += s * xi1;
                }
            }
            __syncwarp();   // protect smem buffers before next stage restages
        }
    }

    // ---- scale by -0.5, transpose through smem, store coalesced ----
#pragma unroll
    for (int r = 0; r < 3; r++) {
        float4 a, b;
        a.x = -0.5f * accr[4*r+0]; a.y = -0.5f * accr[4*r+1];
        a.z = -0.5f * accr[4*r+2]; a.w = -0.5f * accr[4*r+3];
        b.x = -0.5f * acci[4*r+0]; b.y = -0.5f * acci[4*r+1];
        b.z = -0.5f * acci[4*r+2]; b.w = -0.5f * acci[4*r+3];
        sPr4[w][lane * 3 + r] = a;     // stride-3 float4: conflict-free
        sPi4[w][lane * 3 + r] = b;
    }
    __syncwarp();
    float4* out4 = reinterpret_cast<float4*>(out);
#pragma unroll
    for (int r = 0; r < 3; r++) {
        const int j = r * 32 + lane;
        out4[(size_t)base_w * 3 + j]                  = sPr4[w][j];
        out4[(size_t)(VOL + base_w) * 3 + j]          = sPi4[w][j];
    }
}

extern "C" void kernel_launch(void* const* d_in, const int* in_sizes, int n_in,
                              void* d_out, int out_size) {
    const float* psi_re = (const float*)d_in[0];
    const float* psi_im = (const float*)d_in[1];
    const float* U_re   = (const float*)d_in[2];
    const float* U_im   = (const float*)d_in[3];
    // d_in[4..7]: projector matrices — fixed DeGrand-Rossi I -/+ gamma_mu,
    // rank-2 structure exploited analytically.
    float* out = (float*)d_out;

    dslash_kernel<<<VOL / NT, NT>>>(psi_re, psi_im, U_re, U_im, out);
}

// round 9
// speedup vs baseline: 1.2852x; 1.0864x over previous
#include <cuda_runtime.h>
#include <cuda_bf16.h>

// Wilson Dslash, 32^4 lattice, half-spinor formulation.
// L1-wavefront-bound regime: psi neighbor loads are direct LDG.128 (wavefront-
// equal to smem staging, fewer instructions), issued before U staging so their
// latency hides under it. U staged warp-locally (coalesced scalar, conflict-free
// stride-9 readback). t-axis (fastest, extent 32 == warp) hops reuse the warp's
// own psi/U line staged once in smem. Dagger handled by a warp-uniform branch
// with static indices (no selects; conj signs fold into FFMA operands).

#define LAT 32
#define VOL (LAT * LAT * LAT * LAT)
#define NT 256
#define NWARP (NT / 32)

__global__ __launch_bounds__(NT, 2)
void dslash_kernel(const float* __restrict__ psi_re, const float* __restrict__ psi_im,
                   const float* __restrict__ U_re,   const float* __restrict__ U_im,
                   float* __restrict__ out)
{
    __shared__ float4 sPr4[NWARP][96];   // own t-line of psi re (32 sites x 3 float4)
    __shared__ float4 sPi4[NWARP][96];
    __shared__ float  sUr[NWARP][288];   // one t-line of U (32 sites x 9)
    __shared__ float  sUi[NWARP][288];

    const int tid    = threadIdx.x;
    const int lane   = tid & 31;
    const int w      = tid >> 5;
    const int base_w = blockIdx.x * NT + w * 32;   // 32-aligned t-line base
    const int site   = base_w + lane;

    const float4* psi_re4 = reinterpret_cast<const float4*>(psi_re);
    const float4* psi_im4 = reinterpret_cast<const float4*>(psi_im);

    float accr[12], acci[12];
#pragma unroll
    for (int k = 0; k < 12; k++) { accr[k] = 0.f; acci[k] = 0.f; }

#pragma unroll
    for (int mu = 0; mu < 4; mu++) {
        const int shift = (mu == 0) ? 15 : (mu == 1) ? 10 : (mu == 2) ? 5 : 0;
        const int sm = 1 << shift;
        const int cmw = (base_w >> shift) & 31;            // warp-uniform coord
        const int fdelta = (cmw == 31) ? -31 * sm : sm;    // +mu line offset
        const int bdelta = (cmw == 0)  ?  31 * sm : -sm;   // -mu line offset

#pragma unroll 1
        for (int hop = 0; hop < 2; hop++) {   // 0 = fwd (P-, U), 1 = bwd (P+, U^dag)
            const float s = hop ? 1.f : -1.f;

            float pr[12], pi[12];

            if (mu < 3) {
                // ---- direct psi neighbor load, issued EARLY (hides under U staging) ----
                const int nb = site + (hop ? bdelta : fdelta);
                const float4* q4r = &psi_re4[(size_t)nb * 3];
                const float4* q4i = &psi_im4[(size_t)nb * 3];
                float4 ar[3], ai[3];
#pragma unroll
                for (int r = 0; r < 3; r++) { ar[r] = q4r[r]; ai[r] = q4i[r]; }

                // ---- stage U t-line (coalesced). fwd: own line; bwd: -mu line ----
                const int ubase = hop ? (base_w + bdelta) : base_w;
#pragma unroll
                for (int it = 0; it < 9; it++) {
                    const int idx = it * 32 + lane;
                    const int l = idx / 9;
                    const int k = idx - l * 9;
                    const size_t g = ((size_t)(ubase + l) * 4 + mu) * 9 + k;
                    sUr[w][idx] = U_re[g];
                    sUi[w][idx] = U_im[g];
                }
                __syncwarp();

#pragma unroll
                for (int r = 0; r < 3; r++) {
                    pr[4*r+0] = ar[r].x; pr[4*r+1] = ar[r].y;
                    pr[4*r+2] = ar[r].z; pr[4*r+3] = ar[r].w;
                    pi[4*r+0] = ai[r].x; pi[4*r+1] = ai[r].y;
                    pi[4*r+2] = ai[r].z; pi[4*r+3] = ai[r].w;
                }
            } else {
                // ---- mu==3 (t axis == lane): stage own psi+U line once at hop 0 ----
                if (hop == 0) {
#pragma unroll
                    for (int r = 0; r < 3; r++) {
                        const int j = r * 32 + lane;
                        sPr4[w][j] = psi_re4[(size_t)base_w * 3 + j];
                        sPi4[w][j] = psi_im4[(size_t)base_w * 3 + j];
                    }
#pragma unroll
                    for (int it = 0; it < 9; it++) {
                        const int idx = it * 32 + lane;
                        const int l = idx / 9;
                        const int k = idx - l * 9;
                        const size_t g = ((size_t)(base_w + l) * 4 + 3) * 9 + k;
                        sUr[w][idx] = U_re[g];
                        sUi[w][idx] = U_im[g];
                    }
                    __syncwarp();
                }
                // neighbor site within the line (conflict-free LDS.128, stride-3 float4)
                const int psl = (lane + (hop ? 31 : 1)) & 31;
#pragma unroll
                for (int r = 0; r < 3; r++) {
                    float4 a = sPr4[w][psl * 3 + r];
                    pr[4*r+0] = a.x; pr[4*r+1] = a.y; pr[4*r+2] = a.z; pr[4*r+3] = a.w;
                    float4 b = sPi4[w][psl * 3 + r];
                    pi[4*r+0] = b.x; pi[4*r+1] = b.y; pi[4*r+2] = b.z; pi[4*r+3] = b.w;
                }
            }

            // ---- project to half-spinor (mu static, s runtime; FFMA-neutral) ----
            float hr0[3], hi0[3], hr1[3], hi1[3];
#pragma unroll
            for (int c = 0; c < 3; c++) {
                if (mu == 0) {          // h0 = p0 + s*i*p3 ; h1 = p1 + s*i*p2
                    hr0[c] = pr[c]   - s * pi[9+c];  hi0[c] = pi[c]   + s * pr[9+c];
                    hr1[c] = pr[3+c] - s * pi[6+c];  hi1[c] = pi[3+c] + s * pr[6+c];
                } else if (mu == 1) {   // h0 = p0 - s*p3 ; h1 = p1 + s*p2
                    hr0[c] = pr[c]   - s * pr[9+c];  hi0[c] = pi[c]   - s * pi[9+c];
                    hr1[c] = pr[3+c] + s * pr[6+c];  hi1[c] = pi[3+c] + s * pi[6+c];
                } else if (mu == 2) {   // h0 = p0 + s*i*p2 ; h1 = p1 - s*i*p3
                    hr0[c] = pr[c]   - s * pi[6+c];  hi0[c] = pi[c]   + s * pr[6+c];
                    hr1[c] = pr[3+c] + s * pi[9+c];  hi1[c] = pi[3+c] - s * pr[9+c];
                } else {                // h0 = p0 + s*p2 ; h1 = p1 + s*p3
                    hr0[c] = pr[c]   + s * pr[6+c];  hi0[c] = pi[c]   + s * pi[6+c];
                    hr1[c] = pr[3+c] + s * pr[9+c];  hi1[c] = pi[3+c] + s * pi[9+c];
                }
            }

            // ---- U read + color matvec: static per-hop branch (no selects;
            //      dagger conj signs folded into the FFMA expressions) ----
            const int usl = (mu == 3 && hop) ? ((lane + 31) & 31) : lane;
            const float* br = &sUr[w][usl * 9];
            const float* bi = &sUi[w][usl * 9];

            float xr0[3], xi0[3], xr1[3], xi1[3];
            if (hop == 0) {
#pragma unroll
                for (int i = 0; i < 3; i++) {
                    float r0 = 0.f, m0 = 0.f, r1 = 0.f, m1 = 0.f;
#pragma unroll
                    for (int j = 0; j < 3; j++) {
                        const float a = br[3*i+j], b = bi[3*i+j];
                        r0 += a * hr0[j] - b * hi0[j];
                        m0 += a * hi0[j] + b * hr0[j];
                        r1 += a * hr1[j] - b * hi1[j];
                        m1 += a * hi1[j] + b * hr1[j];
                    }
                    xr0[i] = r0; xi0[i] = m0; xr1[i] = r1; xi1[i] = m1;
                }
            } else {
#pragma unroll
                for (int i = 0; i < 3; i++) {
                    float r0 = 0.f, m0 = 0.f, r1 = 0.f, m1 = 0.f;
#pragma unroll
                    for (int j = 0; j < 3; j++) {
                        const float a = br[3*j+i], b = bi[3*j+i];   // U^dag: transpose, conj
                        r0 += a * hr0[j] + b * hi0[j];
                        m0 += a * hi0[j] - b * hr0[j];
                        r1 += a * hr1[j] + b * hi1[j];
                        m1 += a * hi1[j] - b * hr1[j];
                    }
                    xr0[i] = r0; xi0[i] = m0; xr1[i] = r1; xi1[i] = m1;
                }
            }

            // ---- accumulate with spin reconstruction ----
#pragma unroll
            for (int i = 0; i < 3; i++) {
                accr[i]   += xr0[i];  acci[i]   += xi0[i];
                accr[3+i] += xr1[i];  acci[3+i] += xi1[i];
                if (mu == 0) {          // acc2 += -s*i*x1 ; acc3 += -s*i*x0
                    accr[6+i] += s * xi1[i];  acci[6+i] -= s * xr1[i];
                    accr[9+i] += s * xi0[i];  acci[9+i] -= s * xr0[i];
                } else if (mu == 1) {   // acc2 += s*x1 ; acc3 += -s*x0
                    accr[6+i] += s * xr1[i];  acci[6+i] += s * xi1[i];
                    accr[9+i] -= s * xr0[i];  acci[9+i] -= s * xi0[i];
                } else if (mu == 2) {   // acc2 += -s*i*x0 ; acc3 += s*i*x1
                    accr[6+i] += s * xi0[i];  acci[6+i] -= s * xr0[i];
                    accr[9+i] -= s * xi1[i];  acci[9+i] += s * xr1[i];
                } else {                // acc2 += s*x0 ; acc3 += s*x1
                    accr[6+i] += s * xr0[i];  acci[6+i] += s * xi0[i];
                    accr[9+i] += s * xr1[i];  acci[9+i] += s * xi1[i];
                }
            }
            __syncwarp();   // U (and for mu==3, psi) buffers reused next stage
        }
    }

    // ---- scale by -0.5 and store directly (wavefront-equal to transpose) ----
    float* orp = out + (size_t)site * 12;
    float* oip = out + (size_t)VOL * 12 + (size_t)site * 12;
#pragma unroll
    for (int k = 0; k < 3; k++) {
        float4 a, b;
        a.x = -0.5f * accr[4*k+0]; a.y = -0.5f * accr[4*k+1];
        a.z = -0.5f * accr[4*k+2]; a.w = -0.5f * accr[4*k+3];
        b.x = -0.5f * acci[4*k+0]; b.y = -0.5f * acci[4*k+1];
        b.z = -0.5f * acci[4*k+2]; b.w = -0.5f * acci[4*k+3];
        reinterpret_cast<float4*>(orp)[k] = a;
        reinterpret_cast<float4*>(oip)[k] = b;
    }
}

extern "C" void kernel_launch(void* const* d_in, const int* in_sizes, int n_in,
                              void* d_out, int out_size) {
    const float* psi_re = (const float*)d_in[0];
    const float* psi_im = (const float*)d_in[1];
    const float* U_re   = (const float*)d_in[2];
    const float* U_im   = (const float*)d_in[3];
    // d_in[4..7]: projector matrices — fixed DeGrand-Rossi I -/+ gamma_mu,
    // rank-2 structure exploited analytically.
    float* out = (float*)d_out;

    dslash_kernel<<<VOL / NT, NT>>>(psi_re, psi_im, U_re, U_im, out);
}